// round 4
// baseline (speedup 1.0000x reference)
#include <cuda_runtime.h>
#include <cstdint>

// Problem constants (fixed by the dataset)
#define EMBED_DIM   64
#define MAX_ITEMS   500096      // >= 500,000, padded
#define MAX_EDGES   2000128     // >= 2,000,000, padded

// Scan config: 256 threads x 8 items = 2048-element tiles
#define SCAN_TPB    256
#define SCAN_IPT    8
#define SCAN_TILE   (SCAN_TPB * SCAN_IPT)
#define MAX_TILES   256         // ceil(500000/2048) = 245

// Scratch (device globals — no cudaMalloc allowed)
__device__ int g_cnt[MAX_ITEMS];        // in-degree per item (build only)
__device__ int g_rowptr[MAX_ITEMS];     // exclusive scan of counts
__device__ int g_cursor[MAX_ITEMS];     // fill cursor (copy of rowptr)
__device__ int g_srcid[MAX_EDGES];      // CSR values: user index per slot
__device__ int g_ticket;                // scan tile ticket
__device__ unsigned long long g_state[MAX_TILES]; // (sum<<32)|flag; 1=agg,2=prefix

// ---------------------------------------------------------------------------
// 1) reset: zero counts + scan state + ticket
__global__ void k_zero(int n_item, int n_tiles) {
    int i = blockIdx.x * blockDim.x + threadIdx.x;
    if (i < n_item) g_cnt[i] = 0;
    if (i < n_tiles) g_state[i] = 0ULL;
    if (i == 0) g_ticket = 0;
}

// 2) histogram of edge_dst
__global__ void k_hist(const int* __restrict__ dst, int E) {
    int i = blockIdx.x * blockDim.x + threadIdx.x;
    if (i < E) atomicAdd(&g_cnt[__ldg(&dst[i])], 1);
}

// 3) single-pass exclusive scan with decoupled lookback.
//    Writes g_rowptr and g_cursor.
__global__ __launch_bounds__(SCAN_TPB)
void k_scan(int n) {
    __shared__ int s_bid;
    __shared__ int s_exc;
    __shared__ int s_total;
    __shared__ int s_wsum[SCAN_TPB / 32];

    if (threadIdx.x == 0) s_bid = atomicAdd(&g_ticket, 1);
    __syncthreads();
    int bid = s_bid;

    int base = bid * SCAN_TILE + threadIdx.x * SCAN_IPT;
    int v[SCAN_IPT];
    #pragma unroll
    for (int k = 0; k < SCAN_IPT; k++) {
        int idx = base + k;
        v[k] = (idx < n) ? g_cnt[idx] : 0;
    }
    // thread-local inclusive
    #pragma unroll
    for (int k = 1; k < SCAN_IPT; k++) v[k] += v[k - 1];
    int tsum = v[SCAN_IPT - 1];

    // warp inclusive scan of per-thread sums
    int lane = threadIdx.x & 31, wid = threadIdx.x >> 5;
    int inc = tsum;
    #pragma unroll
    for (int o = 1; o < 32; o <<= 1) {
        int t = __shfl_up_sync(0xffffffffu, inc, o);
        if (lane >= o) inc += t;
    }
    if (lane == 31) s_wsum[wid] = inc;
    __syncthreads();
    if (wid == 0 && lane < (SCAN_TPB / 32)) {
        int w = s_wsum[lane];
        int wi = w;
        #pragma unroll
        for (int o = 1; o < (SCAN_TPB / 32); o <<= 1) {
            int t = __shfl_up_sync((1u << (SCAN_TPB / 32)) - 1u, wi, o);
            if (lane >= o) wi += t;
        }
        s_wsum[lane] = wi - w;   // exclusive warp offset
    }
    __syncthreads();
    int texc = s_wsum[wid] + inc - tsum;  // thread's exclusive offset in block

    // last thread publishes block aggregate (or full prefix for tile 0)
    if (threadIdx.x == SCAN_TPB - 1) {
        int blockTotal = s_wsum[wid] + inc;
        s_total = blockTotal;
        unsigned long long st = ((unsigned long long)(unsigned)blockTotal << 32)
                              | (bid == 0 ? 2ULL : 1ULL);
        atomicExch(&g_state[bid], st);
    }

    // thread 0: decoupled lookback
    if (threadIdx.x == 0) {
        int exc = 0;
        for (int p = bid - 1; p >= 0; ) {
            unsigned long long s;
            do { s = atomicAdd(&g_state[p], 0ULL); } while ((s & 3ULL) == 0ULL);
            int val = (int)(unsigned)(s >> 32);
            exc += val;
            if ((s & 3ULL) == 2ULL) break;
            p--;
        }
        s_exc = exc;
    }
    __syncthreads();

    // publish inclusive prefix for successors
    if (threadIdx.x == 0 && bid > 0) {
        unsigned long long st =
            ((unsigned long long)(unsigned)(s_exc + s_total) << 32) | 2ULL;
        atomicExch(&g_state[bid], st);
    }

    int off = s_exc + texc;
    #pragma unroll
    for (int k = 0; k < SCAN_IPT; k++) {
        int idx = base + k;
        if (idx < n) {
            int ex = off + (k > 0 ? v[k - 1] : 0);
            g_rowptr[idx] = ex;
            g_cursor[idx] = ex;
        }
    }
}

// 4) fill CSR slots with source user id
__global__ void k_fill(const int* __restrict__ src, const int* __restrict__ dst, int E) {
    int i = blockIdx.x * blockDim.x + threadIdx.x;
    if (i < E) {
        int pos = atomicAdd(&g_cursor[__ldg(&dst[i])], 1);
        g_srcid[pos] = __ldg(&src[i]);
    }
}

// 5) gather-mean: one warp per item, lane owns a float2 slice (2*32 = 64 dims).
//    deg from rowptr deltas; warp-uniform broadcast index loads; 4-way MLP
//    unroll; streaming store so the 128MB output doesn't evict user rows.
__global__ __launch_bounds__(256)
void k_gather(const float* __restrict__ user, float* __restrict__ out,
              int n_item, int E) {
    int warp_in_block = threadIdx.x >> 5;
    int lane = threadIdx.x & 31;
    int item = blockIdx.x * (blockDim.x >> 5) + warp_in_block;
    if (item >= n_item) return;

    int start = __ldg(&g_rowptr[item]);
    int end   = (item + 1 < n_item) ? __ldg(&g_rowptr[item + 1]) : E;
    int deg   = end - start;

    const float2* __restrict__ U = reinterpret_cast<const float2*>(user);

    float ax0 = 0.f, ay0 = 0.f, ax1 = 0.f, ay1 = 0.f;

    int j = 0;
    for (; j + 4 <= deg; j += 4) {
        int u0 = __ldg(&g_srcid[start + j + 0]);
        int u1 = __ldg(&g_srcid[start + j + 1]);
        int u2 = __ldg(&g_srcid[start + j + 2]);
        int u3 = __ldg(&g_srcid[start + j + 3]);
        float2 v0 = __ldg(&U[(size_t)u0 * 32 + lane]);
        float2 v1 = __ldg(&U[(size_t)u1 * 32 + lane]);
        float2 v2 = __ldg(&U[(size_t)u2 * 32 + lane]);
        float2 v3 = __ldg(&U[(size_t)u3 * 32 + lane]);
        ax0 += v0.x; ay0 += v0.y;
        ax1 += v1.x; ay1 += v1.y;
        ax0 += v2.x; ay0 += v2.y;
        ax1 += v3.x; ay1 += v3.y;
    }
    for (; j < deg; j++) {
        int u = __ldg(&g_srcid[start + j]);
        float2 v = __ldg(&U[(size_t)u * 32 + lane]);
        ax0 += v.x; ay0 += v.y;
    }

    float sc = (deg > 0) ? (1.0f / (float)deg) : 0.0f;
    float2 r;
    r.x = (ax0 + ax1) * sc;
    r.y = (ay0 + ay1) * sc;
    __stcs(reinterpret_cast<float2*>(out) + (size_t)item * 32 + lane, r);
}

// ---------------------------------------------------------------------------
extern "C" void kernel_launch(void* const* d_in, const int* in_sizes, int n_in,
                              void* d_out, int out_size) {
    const float* user_embed = (const float*)d_in[0];
    // d_in[1] (item_embed) unused by the reference computation
    const int* edge_src = (const int*)d_in[2];
    const int* edge_dst = (const int*)d_in[3];

    int n_item = in_sizes[1] / EMBED_DIM;   // 500,000
    int E      = in_sizes[2];               // 2,000,000

    float* out = (float*)d_out;

    int n_tiles = (n_item + SCAN_TILE - 1) / SCAN_TILE;   // 245

    k_zero  <<<(n_item + 255) / 256, 256>>>(n_item, n_tiles);
    k_hist  <<<(E + 255) / 256, 256>>>(edge_dst, E);
    k_scan  <<<n_tiles, SCAN_TPB>>>(n_item);
    k_fill  <<<(E + 255) / 256, 256>>>(edge_src, edge_dst, E);
    k_gather<<<(n_item + 7) / 8, 256>>>(user_embed, out, n_item, E);
}

// round 10
// speedup vs baseline: 1.1926x; 1.1926x over previous
#include <cuda_runtime.h>
#include <cstdint>

// Problem constants (fixed by the dataset)
#define EMBED_DIM   64
#define MAX_ITEMS   500096      // >= 500,000, padded
#define MAX_EDGES   2000128     // >= 2,000,000, padded
#define BUCKET      16          // fast-path slots per item (P(deg>16) ~ 2e-7 here)

// Scratch (device globals — no cudaMalloc allowed)
__device__ int g_cnt[MAX_ITEMS];              // in-degree per item
__device__ int g_bucket[MAX_ITEMS * BUCKET];  // first BUCKET source ids per item
__device__ int g_ovf_n;                       // overflow entry count
__device__ int g_ovf_d[MAX_EDGES];            // overflow: dst
__device__ int g_ovf_s[MAX_EDGES];            // overflow: src

// ---------------------------------------------------------------------------
// 1) reset counts + overflow counter
__global__ void k_zero(int n_item) {
    int i = blockIdx.x * blockDim.x + threadIdx.x;
    if (i < n_item) g_cnt[i] = 0;
    if (i == 0) g_ovf_n = 0;
}

// 2) single-pass bucket fill: histogram + slot assignment fused.
__device__ __forceinline__ void fill_one(int d, int s) {
    int pos = atomicAdd(&g_cnt[d], 1);
    if (pos < BUCKET) {
        g_bucket[d * BUCKET + pos] = s;
    } else {
        int o = atomicAdd(&g_ovf_n, 1);
        g_ovf_d[o] = d;
        g_ovf_s[o] = s;
    }
}

__global__ void k_fillb(const int* __restrict__ src, const int* __restrict__ dst, int E) {
    int i = blockIdx.x * blockDim.x + threadIdx.x;
    int e = i * 4;
    if (e + 4 <= E) {
        int4 d4 = __ldg(reinterpret_cast<const int4*>(dst) + i);
        int4 s4 = __ldg(reinterpret_cast<const int4*>(src) + i);
        fill_one(d4.x, s4.x);
        fill_one(d4.y, s4.y);
        fill_one(d4.z, s4.z);
        fill_one(d4.w, s4.w);
    } else if (e < E) {
        for (int k = e; k < E; k++) fill_one(__ldg(&dst[k]), __ldg(&src[k]));
    }
}

// 3) gather-mean: one HALF-WARP (16 lanes) per item; lane owns a float4
//    slice (16 * 16B = 256B row). Row reads are single LDG.128 per group,
//    fully coalesced. Index fetches are vectorized int4 (64B-aligned bucket
//    rows) half-warp-uniform broadcasts. Dual accumulators break FADD chain.
__global__ __launch_bounds__(256)
void k_gather(const float* __restrict__ user, float* __restrict__ out, int n_item) {
    int lane16 = threadIdx.x & 15;
    int hw_in_block = threadIdx.x >> 4;                 // 16 half-warps per block
    int item = blockIdx.x * (blockDim.x >> 4) + hw_in_block;
    if (item >= n_item) return;

    int deg = __ldg(&g_cnt[item]);
    const int4* bk4 = reinterpret_cast<const int4*>(&g_bucket[item * BUCKET]);
    const float4* __restrict__ U = reinterpret_cast<const float4*>(user);

    float ax0 = 0.f, ay0 = 0.f, az0 = 0.f, aw0 = 0.f;
    float ax1 = 0.f, ay1 = 0.f, az1 = 0.f, aw1 = 0.f;

    int m = deg < BUCKET ? deg : BUCKET;
    int j = 0;
    for (; j + 4 <= m; j += 4) {
        int4 u = __ldg(bk4 + (j >> 2));                 // 4 indices in one LDG.128
        float4 v0 = __ldg(&U[(size_t)u.x * 16 + lane16]);
        float4 v1 = __ldg(&U[(size_t)u.y * 16 + lane16]);
        float4 v2 = __ldg(&U[(size_t)u.z * 16 + lane16]);
        float4 v3 = __ldg(&U[(size_t)u.w * 16 + lane16]);
        ax0 += v0.x; ay0 += v0.y; az0 += v0.z; aw0 += v0.w;
        ax1 += v1.x; ay1 += v1.y; az1 += v1.z; aw1 += v1.w;
        ax0 += v2.x; ay0 += v2.y; az0 += v2.z; aw0 += v2.w;
        ax1 += v3.x; ay1 += v3.y; az1 += v3.z; aw1 += v3.w;
    }
    const int* bk = reinterpret_cast<const int*>(bk4);
    for (; j < m; j++) {
        int u = __ldg(bk + j);
        float4 v = __ldg(&U[(size_t)u * 16 + lane16]);
        ax0 += v.x; ay0 += v.y; az0 += v.z; aw0 += v.w;
    }

    // slow path: items whose degree exceeded the bucket scan the overflow list
    if (deg > BUCKET) {
        int ovn = g_ovf_n;
        for (int t = 0; t < ovn; t++) {
            if (__ldg(&g_ovf_d[t]) == item) {
                int u = __ldg(&g_ovf_s[t]);
                float4 v = __ldg(&U[(size_t)u * 16 + lane16]);
                ax0 += v.x; ay0 += v.y; az0 += v.z; aw0 += v.w;
            }
        }
    }

    float sc = (deg > 0) ? (1.0f / (float)deg) : 0.0f;
    float4 r;
    r.x = (ax0 + ax1) * sc;
    r.y = (ay0 + ay1) * sc;
    r.z = (az0 + az1) * sc;
    r.w = (aw0 + aw1) * sc;
    reinterpret_cast<float4*>(out)[(size_t)item * 16 + lane16] = r;
}

// ---------------------------------------------------------------------------
extern "C" void kernel_launch(void* const* d_in, const int* in_sizes, int n_in,
                              void* d_out, int out_size) {
    const float* user_embed = (const float*)d_in[0];
    // d_in[1] (item_embed) unused by the reference computation
    const int* edge_src = (const int*)d_in[2];
    const int* edge_dst = (const int*)d_in[3];

    int n_item = in_sizes[1] / EMBED_DIM;   // 500,000
    int E      = in_sizes[2];               // 2,000,000

    float* out = (float*)d_out;

    int n_thr = (E + 3) / 4;                // 4 edges per thread

    k_zero  <<<(n_item + 255) / 256, 256>>>(n_item);
    k_fillb <<<(n_thr + 255) / 256, 256>>>(edge_src, edge_dst, E);
    k_gather<<<(n_item + 15) / 16, 256>>>(user_embed, out, n_item);   // 16 items/block
}